// round 8
// baseline (speedup 1.0000x reference)
#include <cuda_runtime.h>
#include <cuda_fp16.h>
#include <cstdint>
#include <cstddef>

// ---------------------------------------------------------------------------
// Bidirectional GRU, B=4096 T=16 I=H=1024.
//   Gx = X @ Wxp^T  (permuted cols, shared by both directions)
//   per step: ONE fused kernel (GEMM h@Whp^T + gates) per direction-pair.
// Fused epilogue v2: accumulators are exchanged through shared memory
// (reusing the cp.async stage buffers), then a gate phase with lane=j mapping
// so ALL global traffic is coalesced. Mainloop identical to the proven R5/R7
// config: 4 warps, 64x48 warp tiles, BK=64, 3 stages, ROWB=144, 2 CTAs/SM.
// Weight permutation period 48 = [16 r | 16 z | 16 t].
// ---------------------------------------------------------------------------

namespace {
constexpr int B_ = 4096, T_ = 16, H_ = 1024;
constexpr int N3 = 3 * H_, K_ = 1024;

// Gx GEMM (R5 config): 128x128 tile, BK=64, 3 stages, 2 CTA/SM
constexpr int GX_BM = 128, GX_BN = 128, GX_BK = 64;
constexpr int GX_NKT = K_ / GX_BK;
constexpr int GX_NST = 3;
constexpr int GX_ROWB = 144;
constexpr int GX_A = GX_BM * GX_ROWB;
constexpr int GX_STAGE = 2 * GX_A;
constexpr int GX_SMEM = GX_NST * GX_STAGE;      // 110592

// fused step kernel: 128x96 tile, BK=64, 3 stages, 128 threads, 2 CTA/SM
constexpr int ST_BM = 128, ST_BN = 96, ST_BK = 64;
constexpr int ST_NKT = K_ / ST_BK;              // 16
constexpr int ST_NST = 3;
constexpr int ST_ROWB = 144;
constexpr int ST_A = ST_BM * ST_ROWB;           // 18432
constexpr int ST_B = ST_BN * ST_ROWB;           // 13824
constexpr int ST_STAGE = ST_A + ST_B;           // 32256
constexpr int ST_SMEM = ST_NST * ST_STAGE;      // 96768
constexpr int C_PITCH = 98;                     // fp32 exchange tile pitch
}

// scratch (static device allocations; no runtime alloc allowed)
__device__ __align__(256) __half g_gx16[(size_t)B_ * T_ * N3];  // permuted x-projections
__device__ __align__(256) float  g_h [(size_t)4 * B_ * H_];     // fp32 h ping-pong
__device__ __align__(256) __half g_h16[(size_t)4 * B_ * H_];    // fp16 mirror of h
__device__ __align__(256) __half g_x16[(size_t)B_ * T_ * K_];   // fp16 x
__device__ __align__(256) __half g_wxp[(size_t)N3 * K_];        // permuted weights (x)
__device__ __align__(256) __half g_whp[(size_t)N3 * K_];        // permuted weights (h)
__device__ __align__(256) float  g_br[H_], g_bz[H_], g_bti[H_], g_bth[H_];

// ------------------------------ PTX helpers --------------------------------
__device__ __forceinline__ uint32_t smem_u32(const void* p) {
    uint32_t a;
    asm("{.reg .u64 t; cvta.to.shared.u64 t, %1; cvt.u32.u64 %0, t;}" : "=r"(a) : "l"(p));
    return a;
}
__device__ __forceinline__ void cp16(uint32_t d, const void* s) {
    asm volatile("cp.async.cg.shared.global [%0], [%1], 16;" :: "r"(d), "l"(s));
}
__device__ __forceinline__ void cp_commit() { asm volatile("cp.async.commit_group;"); }
template <int N>
__device__ __forceinline__ void cp_wait() { asm volatile("cp.async.wait_group %0;" :: "n"(N)); }

__device__ __forceinline__ void ldsm4(uint32_t& r0, uint32_t& r1, uint32_t& r2, uint32_t& r3,
                                      uint32_t a) {
    asm volatile("ldmatrix.sync.aligned.m8n8.x4.shared.b16 {%0,%1,%2,%3}, [%4];"
                 : "=r"(r0), "=r"(r1), "=r"(r2), "=r"(r3) : "r"(a));
}
__device__ __forceinline__ void mma16816(float c[4], const uint32_t a[4], const uint32_t b[2]) {
    asm volatile(
        "mma.sync.aligned.m16n8k16.row.col.f32.f16.f16.f32 "
        "{%0,%1,%2,%3},{%4,%5,%6,%7},{%8,%9},{%0,%1,%2,%3};"
        : "+f"(c[0]), "+f"(c[1]), "+f"(c[2]), "+f"(c[3])
        : "r"(a[0]), "r"(a[1]), "r"(a[2]), "r"(a[3]), "r"(b[0]), "r"(b[1]));
}
__device__ __forceinline__ float sigmoidf_(float x) { return 1.f / (1.f + expf(-x)); }

// -------------------------- Gx GEMM (R5 config) -----------------------------
__global__ __launch_bounds__(128, 2)
void gemm_f16(const __half* __restrict__ Ag, const __half* __restrict__ Wg,
              __half* __restrict__ C)
{
    extern __shared__ __align__(128) char smem[];
    const uint32_t sb = smem_u32(smem);
    const int tid = threadIdx.x, warp = tid >> 5, lane = tid & 31;
    const int n0 = blockIdx.x * GX_BN, mb = blockIdx.y * GX_BM;

    const __half* A = Ag + (size_t)mb * K_;
    const __half* W = Wg + (size_t)n0 * K_;

    const int wm = (warp & 1) * 64, wn = (warp >> 1) * 64;
    const uint32_t aFrag = sb + (uint32_t)(wm + (lane & 15)) * GX_ROWB + ((lane >> 4) & 1) * 16;
    const uint32_t bFrag = sb + GX_A +
        (uint32_t)(wn + ((lane >> 4) & 1) * 8 + (lane & 7)) * GX_ROWB + ((lane >> 3) & 1) * 16;

    float acc[4][8][4];
#pragma unroll
    for (int a = 0; a < 4; ++a)
#pragma unroll
        for (int b = 0; b < 8; ++b)
#pragma unroll
            for (int c = 0; c < 4; ++c) acc[a][b][c] = 0.f;

#define GFILL(S, KT)                                                          \
    {                                                                         \
        _Pragma("unroll")                                                     \
        for (int i = 0; i < 8; ++i) {                                         \
            int c = tid + 128 * i;                                            \
            int row = c >> 3, col = c & 7;                                    \
            uint32_t d = sb + (S) * GX_STAGE + row * GX_ROWB + col * 16;      \
            cp16(d, A + (size_t)row * K_ + (KT) * GX_BK + col * 8);           \
            cp16(d + GX_A, W + (size_t)row * K_ + (KT) * GX_BK + col * 8);    \
        }                                                                     \
    }

#pragma unroll
    for (int s = 0; s < GX_NST - 1; ++s) { GFILL(s, s); cp_commit(); }

    int st = 0;
    for (int kt = 0; kt < GX_NKT; ++kt) {
        cp_wait<GX_NST - 2>();
        __syncthreads();
        if (kt + GX_NST - 1 < GX_NKT) {
            int fs = st + 2; if (fs >= GX_NST) fs -= GX_NST;
            GFILL(fs, kt + GX_NST - 1);
        }
        cp_commit();

        const uint32_t aS = aFrag + st * GX_STAGE;
        const uint32_t bS = bFrag + st * GX_STAGE;
#pragma unroll
        for (int ks = 0; ks < 4; ++ks) {
            uint32_t af[4][4], bf[8][2];
#pragma unroll
            for (int mi = 0; mi < 4; ++mi)
                ldsm4(af[mi][0], af[mi][1], af[mi][2], af[mi][3],
                      aS + mi * 16 * GX_ROWB + ks * 32);
#pragma unroll
            for (int nj = 0; nj < 4; ++nj)
                ldsm4(bf[2 * nj][0], bf[2 * nj][1], bf[2 * nj + 1][0], bf[2 * nj + 1][1],
                      bS + nj * 16 * GX_ROWB + ks * 32);
#pragma unroll
            for (int mi = 0; mi < 4; ++mi)
#pragma unroll
                for (int ni = 0; ni < 8; ++ni)
                    mma16816(acc[mi][ni], af[mi], bf[ni]);
        }
        if (++st == GX_NST) st = 0;
    }
#undef GFILL

    __half* crow = C + (size_t)(mb + wm + (lane >> 2)) * N3 + n0 + wn + (lane & 3) * 2;
#pragma unroll
    for (int mi = 0; mi < 4; ++mi) {
#pragma unroll
        for (int ni = 0; ni < 8; ++ni) {
            *reinterpret_cast<__half2*>(crow + (size_t)(mi * 16) * N3 + ni * 8) =
                __floats2half2_rn(acc[mi][ni][0], acc[mi][ni][1]);
            *reinterpret_cast<__half2*>(crow + (size_t)(mi * 16 + 8) * N3 + ni * 8) =
                __floats2half2_rn(acc[mi][ni][2], acc[mi][ni][3]);
        }
    }
}

// --------------- fused step kernel (GEMM + smem-exchange gates) -------------
__global__ __launch_bounds__(128, 2)
void step_f16(float* __restrict__ out, int s, int phase)
{
    extern __shared__ __align__(128) char smem[];
    const uint32_t sb = smem_u32(smem);
    const int tid = threadIdx.x, warp = tid >> 5, lane = tid & 31;
    const int g = lane >> 2, tg = lane & 3;
    const int n0 = blockIdx.x * ST_BN;      // permuted col base
    const int j0 = blockIdx.x * 32;         // hidden-index base (= n0/3)
    const int mb = blockIdx.y * ST_BM;
    const int d  = blockIdx.z;
    const int time = (d == 0) ? s : (T_ - 1 - s);
    const int tout = (d == 0) ? (T_ - 1 - s) : s;

    const __half* A = g_h16 + (size_t)((d * 2 + phase) * B_ + mb) * K_;
    const __half* W = g_whp + (size_t)n0 * K_;

    // warp grid 2(M) x 2(N); warp tile 64 x 48
    const int wm = (warp & 1), wn = (warp >> 1);
    const uint32_t aFrag = sb + (uint32_t)(wm * 64 + (lane & 15)) * ST_ROWB +
                           ((lane >> 4) & 1) * 16;
    const uint32_t bFrag = sb + ST_A +
        (uint32_t)(wn * 48 + ((lane >> 4) & 1) * 8 + (lane & 7)) * ST_ROWB +
        ((lane >> 3) & 1) * 16;

    float acc[4][6][4];
#pragma unroll
    for (int a = 0; a < 4; ++a)
#pragma unroll
        for (int b = 0; b < 6; ++b)
#pragma unroll
            for (int c = 0; c < 4; ++c) acc[a][b][c] = 0.f;

#define SFILL(S, KT)                                                          \
    {                                                                         \
        _Pragma("unroll")                                                     \
        for (int i = 0; i < 8; ++i) {                                         \
            int c = tid + 128 * i;                                            \
            int row = c >> 3, col = c & 7;                                    \
            uint32_t dst = sb + (S) * ST_STAGE + row * ST_ROWB + col * 16;    \
            cp16(dst, A + (size_t)row * K_ + (KT) * ST_BK + col * 8);         \
        }                                                                     \
        _Pragma("unroll")                                                     \
        for (int i = 0; i < 6; ++i) {                                         \
            int c = tid + 128 * i;                                            \
            int row = c >> 3, col = c & 7;                                    \
            uint32_t dst = sb + (S) * ST_STAGE + ST_A + row * ST_ROWB + col * 16; \
            cp16(dst, W + (size_t)row * K_ + (KT) * ST_BK + col * 8);         \
        }                                                                     \
    }

#pragma unroll
    for (int st0 = 0; st0 < ST_NST - 1; ++st0) { SFILL(st0, st0); cp_commit(); }

    int st = 0;
    for (int kt = 0; kt < ST_NKT; ++kt) {
        cp_wait<ST_NST - 2>();
        __syncthreads();
        if (kt + ST_NST - 1 < ST_NKT) {
            int fs = st + 2; if (fs >= ST_NST) fs -= ST_NST;
            SFILL(fs, kt + ST_NST - 1);
        }
        cp_commit();

        const uint32_t aS = aFrag + st * ST_STAGE;
        const uint32_t bS = bFrag + st * ST_STAGE;
#pragma unroll
        for (int ks = 0; ks < 4; ++ks) {
            uint32_t af[4][4], bf[6][2];
#pragma unroll
            for (int mi = 0; mi < 4; ++mi)
                ldsm4(af[mi][0], af[mi][1], af[mi][2], af[mi][3],
                      aS + mi * 16 * ST_ROWB + ks * 32);
#pragma unroll
            for (int nj = 0; nj < 3; ++nj)
                ldsm4(bf[2 * nj][0], bf[2 * nj][1], bf[2 * nj + 1][0], bf[2 * nj + 1][1],
                      bS + nj * 16 * ST_ROWB + ks * 32);
#pragma unroll
            for (int mi = 0; mi < 4; ++mi)
#pragma unroll
                for (int ni = 0; ni < 6; ++ni)
                    mma16816(acc[mi][ni], af[mi], bf[ni]);
        }
        if (++st == ST_NST) st = 0;
    }
#undef SFILL

    // ------------- epilogue: exchange acc through smem, then gates -------------
    cp_wait<0>();
    __syncthreads();                         // all stages done; smem reusable
    float* sC = reinterpret_cast<float*>(smem);   // [128][C_PITCH]
#pragma unroll
    for (int mi = 0; mi < 4; ++mi) {
        const int r0 = wm * 64 + mi * 16 + g;
        const int c0 = wn * 48 + tg * 2;
#pragma unroll
        for (int ni = 0; ni < 6; ++ni) {
            sC[r0 * C_PITCH + c0 + ni * 8]           = acc[mi][ni][0];
            sC[r0 * C_PITCH + c0 + ni * 8 + 1]       = acc[mi][ni][1];
            sC[(r0 + 8) * C_PITCH + c0 + ni * 8]     = acc[mi][ni][2];
            sC[(r0 + 8) * C_PITCH + c0 + ni * 8 + 1] = acc[mi][ni][3];
        }
    }
    __syncthreads();

    // gate phase: lane = local hidden unit (32 per CTA); warp iterates 32 rows
    const int q = lane >> 4, u = lane & 15;
    const int cr = 48 * q + u, cz = cr + 16, ct = cr + 32;
    const int j = j0 + lane;                  // j = 16q + u == lane
    const float br  = g_br[j];
    const float bz  = g_bz[j];
    const float bti = g_bti[j];
    const float bth = g_bth[j];
    const float* hp   = g_h   + (size_t)(d * 2 + phase) * B_ * H_;
    float*       hn   = g_h   + (size_t)(d * 2 + (phase ^ 1)) * B_ * H_;
    __half*      hn16 = g_h16 + (size_t)(d * 2 + (phase ^ 1)) * B_ * H_;

#pragma unroll 4
    for (int i = 0; i < 32; ++i) {
        const int m = warp * 32 + i;
        const int b = mb + m;
        const __half* gxr = g_gx16 + ((size_t)b * T_ + time) * N3 + n0;
        const float xr = __half2float(gxr[cr]);
        const float xz = __half2float(gxr[cz]);
        const float xt = __half2float(gxr[ct]);
        const float pr = sC[m * C_PITCH + cr];
        const float pz = sC[m * C_PITCH + cz];
        const float pt = sC[m * C_PITCH + ct];
        const float hv = hp[(size_t)b * H_ + j];

        const float r = sigmoidf_(pr + xr + br);
        const float z = sigmoidf_(pz + xz + bz);
        const float t = tanhf(xt + bti + r * (pt + bth));
        const float nh = z * t + (1.f - z) * hv;

        hn[(size_t)b * H_ + j] = nh;
        hn16[(size_t)b * H_ + j] = __float2half_rn(nh);
        out[((size_t)b * T_ + tout) * (2 * H_) + (size_t)d * H_ + j] = nh;
    }
}

// ------------------------------ small kernels ------------------------------
__global__ void cvt16(const float* __restrict__ s, __half* __restrict__ d, int n4)
{
    int i = blockIdx.x * blockDim.x + threadIdx.x;
    if (i < n4) {
        float4 v = reinterpret_cast<const float4*>(s)[i];
        __half2 p0 = __floats2half2_rn(v.x, v.y);
        __half2 p1 = __floats2half2_rn(v.z, v.w);
        uint2 u; u.x = *reinterpret_cast<uint32_t*>(&p0); u.y = *reinterpret_cast<uint32_t*>(&p1);
        reinterpret_cast<uint2*>(d)[i] = u;
    }
}

// permuted fp16 weights: period 48 = [16 r | 16 z | 16 t];
// dst col c = 48q + 16*gate + v  <-  {Wzr row j, Wzr row H+j, Wt row j}, j=16q+v.
__global__ void permW(const float* __restrict__ Wzr, const float* __restrict__ Wt,
                      __half* __restrict__ dst)
{
    int i = blockIdx.x * blockDim.x + threadIdx.x;   // over N3 * K/4
    if (i >= N3 * (K_ / 4)) return;
    int c = i >> 8;            // K/4 = 256
    int kk = i & 255;
    int q = c / 48, rem = c % 48, gate = rem >> 4, v = rem & 15;
    int j = 16 * q + v;
    const float* src = (gate == 0) ? Wzr + (size_t)j * K_
                     : (gate == 1) ? Wzr + (size_t)(H_ + j) * K_
                                   : Wt + (size_t)j * K_;
    float4 vv = reinterpret_cast<const float4*>(src)[kk];
    __half2 p0 = __floats2half2_rn(vv.x, vv.y);
    __half2 p1 = __floats2half2_rn(vv.z, vv.w);
    uint2 uu; uu.x = *reinterpret_cast<uint32_t*>(&p0); uu.y = *reinterpret_cast<uint32_t*>(&p1);
    reinterpret_cast<uint2*>(dst + (size_t)c * K_)[kk] = uu;
}

__global__ void bias_prep(const float* __restrict__ b_izr, const float* __restrict__ b_hzr,
                          const float* __restrict__ b_it,  const float* __restrict__ b_ht)
{
    int j = blockIdx.x * blockDim.x + threadIdx.x;
    if (j < H_) {
        g_br[j]  = b_izr[j] + b_hzr[j];
        g_bz[j]  = b_izr[H_ + j] + b_hzr[H_ + j];
        g_bti[j] = b_it[j];
        g_bth[j] = b_ht[j];
    }
}

__global__ void init_h(const float* __restrict__ h0, const float* __restrict__ bih0)
{
    size_t i = (size_t)blockIdx.x * blockDim.x + threadIdx.x;
    if (i < (size_t)B_ * H_) {
        float a = h0[i], b = bih0[i];
        g_h[i] = a;
        g_h[(size_t)2 * B_ * H_ + i] = b;
        g_h16[i] = __float2half_rn(a);
        g_h16[(size_t)2 * B_ * H_ + i] = __float2half_rn(b);
    }
}

// ------------------------------ host side ----------------------------------
extern "C" void kernel_launch(void* const* d_in, const int* in_sizes, int n_in,
                              void* d_out, int out_size)
{
    const float* x     = (const float*)d_in[0];
    const float* h0    = (const float*)d_in[1];
    const float* bih0  = (const float*)d_in[2];
    const float* W_izr = (const float*)d_in[3];
    const float* b_izr = (const float*)d_in[4];
    const float* W_hzr = (const float*)d_in[5];
    const float* b_hzr = (const float*)d_in[6];
    const float* W_it  = (const float*)d_in[7];
    const float* b_it  = (const float*)d_in[8];
    const float* W_ht  = (const float*)d_in[9];
    const float* b_ht  = (const float*)d_in[10];
    float* out = (float*)d_out;
    (void)in_sizes; (void)n_in; (void)out_size;

    void *p_gx = nullptr, *p_x16 = nullptr, *p_wxp = nullptr, *p_whp = nullptr;
    cudaGetSymbolAddress(&p_gx, g_gx16);
    cudaGetSymbolAddress(&p_x16, g_x16);
    cudaGetSymbolAddress(&p_wxp, g_wxp);
    cudaGetSymbolAddress(&p_whp, g_whp);

    cudaFuncSetAttribute(gemm_f16, cudaFuncAttributeMaxDynamicSharedMemorySize, GX_SMEM);
    cudaFuncSetAttribute(step_f16, cudaFuncAttributeMaxDynamicSharedMemorySize, ST_SMEM);

    // prep: permuted fp16 weights, fp16 x, combined biases, h init
    const int PN = N3 * (K_ / 4);
    permW<<<(PN + 255) / 256, 256>>>(W_izr, W_it, (__half*)p_wxp);
    permW<<<(PN + 255) / 256, 256>>>(W_hzr, W_ht, (__half*)p_whp);
    const int XN4 = B_ * T_ * K_ / 4;
    cvt16<<<(XN4 + 255) / 256, 256>>>(x, (__half*)p_x16, XN4);
    bias_prep<<<4, 256>>>(b_izr, b_hzr, b_it, b_ht);
    init_h<<<(B_ * H_ + 255) / 256, 256>>>(h0, bih0);

    // Gx = X @ Wxp^T (permuted columns)
    gemm_f16<<<dim3(N3 / GX_BN, (B_ * T_) / GX_BM, 1), 128, GX_SMEM>>>(
        (const __half*)p_x16, (const __half*)p_wxp, (__half*)p_gx);

    // 16 fused sequential steps, both directions per launch
    int phase = 0;
    for (int s = 0; s < T_; ++s) {
        step_f16<<<dim3(N3 / ST_BN, B_ / ST_BM, 2), 128, ST_SMEM>>>(out, s, phase);
        phase ^= 1;
    }
}

// round 9
// speedup vs baseline: 1.4127x; 1.4127x over previous
#include <cuda_runtime.h>
#include <cuda_fp16.h>
#include <cstdint>
#include <cstddef>

// ---------------------------------------------------------------------------
// Bidirectional GRU, B=4096 T=16 I=H=1024.  (R5 structure — fusion abandoned)
//   Gx = X @ [W_izr; W_it]^T   (one big GEMM, shared by both directions)
//   per step: Gh[d] = h[d] @ [W_hzr; W_ht]^T  (grid.z = 2), fused gate kernel.
// GEMM: fp16 in/out (fp32 accum), mma.sync.m16n8k16 + ldmatrix.x4 + cp.async,
// 128x128 CTA tile, 4 warps (64x64), BK=64, 3 stages, 2 CTAs/SM.
// Gate reads prev fp32 h from `out` (written last step) — no fp32 h ping-pong.
// ---------------------------------------------------------------------------

namespace {
constexpr int B_ = 4096, T_ = 16, H_ = 1024;
constexpr int N3 = 3 * H_, K_ = 1024;
constexpr int BM = 128, BN = 128, BK = 64;   // CTA tile; BK in halfs
constexpr int NKT = K_ / BK;                 // 16 k-iterations
constexpr int NST = 3;                       // cp.async stages
constexpr int ROWB = 144;                    // smem row pitch (128B data + 16B pad)
constexpr int A_BYTES = BM * ROWB;           // 18432
constexpr int STAGE = 2 * A_BYTES;           // 36864 (A + B)
constexpr int SMEM_BYTES = NST * STAGE;      // 110592
}

// scratch (static device allocations; no runtime alloc allowed)
__device__ __align__(256) __half g_gx16[(size_t)B_ * T_ * N3];  // x-projections (fp16)
__device__ __align__(256) __half g_gh16[(size_t)2 * B_ * N3];   // h-projections (fp16)
__device__ __align__(256) float  g_h0 [(size_t)2 * B_ * H_];    // fp32 initial h per dir
__device__ __align__(256) __half g_h16[(size_t)4 * B_ * H_];    // fp16 h ping-pong (GEMM A)
__device__ __align__(256) __half g_x16[(size_t)B_ * T_ * K_];   // fp16 x
__device__ __align__(256) __half g_wx16[(size_t)N3 * K_];       // [W_izr; W_it] fp16
__device__ __align__(256) __half g_wh16[(size_t)N3 * K_];       // [W_hzr; W_ht] fp16

// ------------------------------ PTX helpers --------------------------------
__device__ __forceinline__ uint32_t smem_u32(const void* p) {
    uint32_t a;
    asm("{.reg .u64 t; cvta.to.shared.u64 t, %1; cvt.u32.u64 %0, t;}" : "=r"(a) : "l"(p));
    return a;
}
__device__ __forceinline__ void cp16(uint32_t d, const void* s) {
    asm volatile("cp.async.cg.shared.global [%0], [%1], 16;" :: "r"(d), "l"(s));
}
__device__ __forceinline__ void cp_commit() { asm volatile("cp.async.commit_group;"); }
template <int N>
__device__ __forceinline__ void cp_wait() { asm volatile("cp.async.wait_group %0;" :: "n"(N)); }

__device__ __forceinline__ void ldsm4(uint32_t& r0, uint32_t& r1, uint32_t& r2, uint32_t& r3,
                                      uint32_t a) {
    asm volatile("ldmatrix.sync.aligned.m8n8.x4.shared.b16 {%0,%1,%2,%3}, [%4];"
                 : "=r"(r0), "=r"(r1), "=r"(r2), "=r"(r3) : "r"(a));
}
__device__ __forceinline__ void mma16816(float c[4], const uint32_t a[4], const uint32_t b[2]) {
    asm volatile(
        "mma.sync.aligned.m16n8k16.row.col.f32.f16.f16.f32 "
        "{%0,%1,%2,%3},{%4,%5,%6,%7},{%8,%9},{%0,%1,%2,%3};"
        : "+f"(c[0]), "+f"(c[1]), "+f"(c[2]), "+f"(c[3])
        : "r"(a[0]), "r"(a[1]), "r"(a[2]), "r"(a[3]), "r"(b[0]), "r"(b[1]));
}

// ------------------------------ GEMM kernel --------------------------------
// C[mb:mb+128, n0:n0+128] = A @ W[n,:]^T  (A, W fp16; C fp16, fp32 accum)
__global__ __launch_bounds__(128, 2)
void gemm_f16(const __half* __restrict__ Ag, const __half* __restrict__ Wg,
              __half* __restrict__ Cb, int phase, int recur)
{
    extern __shared__ __align__(128) char smem[];
    const uint32_t sb = smem_u32(smem);
    const int tid = threadIdx.x, warp = tid >> 5, lane = tid & 31;
    const int n0 = blockIdx.x * BN, mb = blockIdx.y * BM, dz = blockIdx.z;

    const __half* A = Ag + (recur ? (size_t)((dz * 2 + phase) * B_ + mb) * K_
                                  : (size_t)mb * K_);
    const __half* W = Wg + (size_t)n0 * K_;
    __half* C = Cb + (size_t)dz * B_ * N3;

    // warp tile: 64 x 64  (warp grid 2 x 2)
    const int wm = (warp & 1) * 64, wn = (warp >> 1) * 64;
    const uint32_t aFrag = sb + (uint32_t)(wm + (lane & 15)) * ROWB + ((lane >> 4) & 1) * 16;
    const uint32_t bFrag = sb + A_BYTES +
        (uint32_t)(wn + ((lane >> 4) & 1) * 8 + (lane & 7)) * ROWB + ((lane >> 3) & 1) * 16;

    float acc[4][8][4];
#pragma unroll
    for (int a = 0; a < 4; ++a)
#pragma unroll
        for (int b = 0; b < 8; ++b)
#pragma unroll
            for (int c = 0; c < 4; ++c) acc[a][b][c] = 0.f;

    // fill: 128 rows x 8 chunks(16B) for A and B; 8 per thread each (128 thr)
#define FILL(S, KT)                                                           \
    {                                                                         \
        _Pragma("unroll")                                                     \
        for (int i = 0; i < 8; ++i) {                                         \
            int c = tid + 128 * i;                                            \
            int row = c >> 3, col = c & 7;                                    \
            uint32_t d = sb + (S) * STAGE + row * ROWB + col * 16;            \
            cp16(d, A + (size_t)row * K_ + (KT) * BK + col * 8);              \
            cp16(d + A_BYTES, W + (size_t)row * K_ + (KT) * BK + col * 8);    \
        }                                                                     \
    }

#pragma unroll
    for (int s = 0; s < NST - 1; ++s) { FILL(s, s); cp_commit(); }

    int st = 0;
    for (int kt = 0; kt < NKT; ++kt) {
        cp_wait<NST - 2>();
        __syncthreads();
        if (kt + NST - 1 < NKT) {
            int fs = st + 2; if (fs >= NST) fs -= NST;
            FILL(fs, kt + NST - 1);
        }
        cp_commit();

        const uint32_t aS = aFrag + st * STAGE;
        const uint32_t bS = bFrag + st * STAGE;
#pragma unroll
        for (int ks = 0; ks < 4; ++ks) {
            uint32_t af[4][4], bf[8][2];
#pragma unroll
            for (int mi = 0; mi < 4; ++mi)
                ldsm4(af[mi][0], af[mi][1], af[mi][2], af[mi][3],
                      aS + mi * 16 * ROWB + ks * 32);
#pragma unroll
            for (int nj = 0; nj < 4; ++nj)
                ldsm4(bf[2 * nj][0], bf[2 * nj][1], bf[2 * nj + 1][0], bf[2 * nj + 1][1],
                      bS + nj * 16 * ROWB + ks * 32);
#pragma unroll
            for (int mi = 0; mi < 4; ++mi)
#pragma unroll
                for (int ni = 0; ni < 8; ++ni)
                    mma16816(acc[mi][ni], af[mi], bf[ni]);
        }
        if (++st == NST) st = 0;
    }
#undef FILL

    // epilogue: fp16 stores (half2 per fragment row-pair)
    __half* crow = C + (size_t)(mb + wm + (lane >> 2)) * N3 + n0 + wn + (lane & 3) * 2;
#pragma unroll
    for (int mi = 0; mi < 4; ++mi) {
#pragma unroll
        for (int ni = 0; ni < 8; ++ni) {
            *reinterpret_cast<__half2*>(crow + (size_t)(mi * 16) * N3 + ni * 8) =
                __floats2half2_rn(acc[mi][ni][0], acc[mi][ni][1]);
            *reinterpret_cast<__half2*>(crow + (size_t)(mi * 16 + 8) * N3 + ni * 8) =
                __floats2half2_rn(acc[mi][ni][2], acc[mi][ni][3]);
        }
    }
}

// ------------------------------ gate kernel --------------------------------
__device__ __forceinline__ float sigmoidf_(float x) { return 1.f / (1.f + expf(-x)); }

__global__ __launch_bounds__(256)
void gate_kernel(const float* __restrict__ b_izr, const float* __restrict__ b_hzr,
                 const float* __restrict__ b_it,  const float* __restrict__ b_ht,
                 float* __restrict__ out, int s, int phase)
{
    const int d   = blockIdx.z;
    const int idx = blockIdx.x * blockDim.x + threadIdx.x;
    const int j4  = idx << 2;
    const int b   = j4 >> 10;
    const int j   = j4 & (H_ - 1);
    const int time = (d == 0) ? s : (T_ - 1 - s);
    const int tout = (d == 0) ? (T_ - 1 - s) : s;

    const __half* gx = g_gx16 + ((size_t)b * T_ + time) * N3;
    const __half* gh = g_gh16 + (size_t)d * B_ * N3 + (size_t)b * N3;

    // previous fp32 h: from init at s=0, else from out written at step s-1
    float4 h;
    if (s == 0) {
        h = *(const float4*)(g_h0 + (size_t)d * B_ * H_ + (size_t)b * H_ + j);
    } else {
        const int tprev = (d == 0) ? (T_ - s) : (s - 1);
        h = *(const float4*)(out + ((size_t)b * T_ + tprev) * (2 * H_) +
                             (size_t)d * H_ + j);
    }
    const size_t hoff = ((size_t)d * 2 + (phase ^ 1)) * B_ * H_ + (size_t)b * H_ + j;

#define LDH4(p) (*reinterpret_cast<const uint2*>(p))
    uint2 uxr = LDH4(gx + j),          uxz = LDH4(gx + H_ + j),      uxt = LDH4(gx + 2 * H_ + j);
    uint2 uhr = LDH4(gh + j),          uhz = LDH4(gh + H_ + j),      uht = LDH4(gh + 2 * H_ + j);
#undef LDH4
    float4 bir = *(const float4*)(b_izr + j);
    float4 biz = *(const float4*)(b_izr + H_ + j);
    float4 bhr = *(const float4*)(b_hzr + j);
    float4 bhz = *(const float4*)(b_hzr + H_ + j);
    float4 bti = *(const float4*)(b_it + j);
    float4 bth = *(const float4*)(b_ht + j);

    float2 xr0 = __half22float2(*reinterpret_cast<__half2*>(&uxr.x));
    float2 xr1 = __half22float2(*reinterpret_cast<__half2*>(&uxr.y));
    float2 xz0 = __half22float2(*reinterpret_cast<__half2*>(&uxz.x));
    float2 xz1 = __half22float2(*reinterpret_cast<__half2*>(&uxz.y));
    float2 xt0 = __half22float2(*reinterpret_cast<__half2*>(&uxt.x));
    float2 xt1 = __half22float2(*reinterpret_cast<__half2*>(&uxt.y));
    float2 hr0 = __half22float2(*reinterpret_cast<__half2*>(&uhr.x));
    float2 hr1 = __half22float2(*reinterpret_cast<__half2*>(&uhr.y));
    float2 hz0 = __half22float2(*reinterpret_cast<__half2*>(&uhz.x));
    float2 hz1 = __half22float2(*reinterpret_cast<__half2*>(&uhz.y));
    float2 ht0 = __half22float2(*reinterpret_cast<__half2*>(&uht.x));
    float2 ht1 = __half22float2(*reinterpret_cast<__half2*>(&uht.y));

    float4 nh;
#define GATE(c, GXR, GHR, GXZ, GHZ, GXT, GHT)                               \
    {                                                                       \
        float rg = sigmoidf_(GXR + GHR + bir.c + bhr.c);                    \
        float zg = sigmoidf_(GXZ + GHZ + biz.c + bhz.c);                    \
        float ht = tanhf(GXT + bti.c + rg * (GHT + bth.c));                 \
        nh.c = zg * ht + (1.f - zg) * h.c;                                  \
    }
    GATE(x, xr0.x, hr0.x, xz0.x, hz0.x, xt0.x, ht0.x)
    GATE(y, xr0.y, hr0.y, xz0.y, hz0.y, xt0.y, ht0.y)
    GATE(z, xr1.x, hr1.x, xz1.x, hz1.x, xt1.x, ht1.x)
    GATE(w, xr1.y, hr1.y, xz1.y, hz1.y, xt1.y, ht1.y)
#undef GATE

    __half2 p0 = __floats2half2_rn(nh.x, nh.y);
    __half2 p1 = __floats2half2_rn(nh.z, nh.w);
    uint2 u; u.x = *reinterpret_cast<uint32_t*>(&p0); u.y = *reinterpret_cast<uint32_t*>(&p1);
    *reinterpret_cast<uint2*>(g_h16 + hoff) = u;
    *(float4*)(out + ((size_t)b * T_ + tout) * (2 * H_) + (size_t)d * H_ + j) = nh;
}

// ------------------------------ small kernels ------------------------------
__global__ void cvt16(const float* __restrict__ s, __half* __restrict__ d, int n4)
{
    int i = blockIdx.x * blockDim.x + threadIdx.x;
    if (i < n4) {
        float4 v = reinterpret_cast<const float4*>(s)[i];
        __half2 p0 = __floats2half2_rn(v.x, v.y);
        __half2 p1 = __floats2half2_rn(v.z, v.w);
        uint2 u; u.x = *reinterpret_cast<uint32_t*>(&p0); u.y = *reinterpret_cast<uint32_t*>(&p1);
        reinterpret_cast<uint2*>(d)[i] = u;
    }
}

__global__ void init_h(const float* __restrict__ h0, const float* __restrict__ bih0)
{
    size_t i = (size_t)blockIdx.x * blockDim.x + threadIdx.x;
    if (i < (size_t)B_ * H_) {
        float a = h0[i], b = bih0[i];
        g_h0[i] = a;
        g_h0[(size_t)B_ * H_ + i] = b;
        g_h16[i] = __float2half_rn(a);                       // dir 0, phase 0
        g_h16[(size_t)2 * B_ * H_ + i] = __float2half_rn(b); // dir 1, phase 0
    }
}

// ------------------------------ host side ----------------------------------
extern "C" void kernel_launch(void* const* d_in, const int* in_sizes, int n_in,
                              void* d_out, int out_size)
{
    const float* x     = (const float*)d_in[0];
    const float* h0    = (const float*)d_in[1];
    const float* bih0  = (const float*)d_in[2];
    const float* W_izr = (const float*)d_in[3];
    const float* b_izr = (const float*)d_in[4];
    const float* W_hzr = (const float*)d_in[5];
    const float* b_hzr = (const float*)d_in[6];
    const float* W_it  = (const float*)d_in[7];
    const float* b_it  = (const float*)d_in[8];
    const float* W_ht  = (const float*)d_in[9];
    const float* b_ht  = (const float*)d_in[10];
    float* out = (float*)d_out;
    (void)in_sizes; (void)n_in; (void)out_size;

    void *p_gx = nullptr, *p_gh = nullptr, *p_x16 = nullptr, *p_h16 = nullptr,
         *p_wx = nullptr, *p_wh = nullptr;
    cudaGetSymbolAddress(&p_gx, g_gx16);
    cudaGetSymbolAddress(&p_gh, g_gh16);
    cudaGetSymbolAddress(&p_x16, g_x16);
    cudaGetSymbolAddress(&p_h16, g_h16);
    cudaGetSymbolAddress(&p_wx, g_wx16);
    cudaGetSymbolAddress(&p_wh, g_wh16);

    cudaFuncSetAttribute(gemm_f16, cudaFuncAttributeMaxDynamicSharedMemorySize, SMEM_BYTES);

    // fp16 conversions
    const int WN4 = 2 * H_ * K_ / 4, WN4b = H_ * K_ / 4, XN4 = B_ * T_ * K_ / 4;
    cvt16<<<(WN4 + 255) / 256, 256>>>(W_izr, (__half*)p_wx, WN4);
    cvt16<<<(WN4b + 255) / 256, 256>>>(W_it, (__half*)p_wx + (size_t)2 * H_ * K_, WN4b);
    cvt16<<<(WN4 + 255) / 256, 256>>>(W_hzr, (__half*)p_wh, WN4);
    cvt16<<<(WN4b + 255) / 256, 256>>>(W_ht, (__half*)p_wh + (size_t)2 * H_ * K_, WN4b);
    cvt16<<<(XN4 + 255) / 256, 256>>>(x, (__half*)p_x16, XN4);
    init_h<<<(B_ * H_ + 255) / 256, 256>>>(h0, bih0);

    // Gx = X @ [W_izr; W_it]^T over all (b, t)
    gemm_f16<<<dim3(N3 / BN, (B_ * T_) / BM, 1), 128, SMEM_BYTES>>>(
        (const __half*)p_x16, (const __half*)p_wx, (__half*)p_gx, 0, 0);

    // 16 sequential steps, both directions per launch
    int phase = 0;
    for (int s = 0; s < T_; ++s) {
        gemm_f16<<<dim3(N3 / BN, B_ / BM, 2), 128, SMEM_BYTES>>>(
            (const __half*)p_h16, (const __half*)p_wh, (__half*)p_gh, phase, 1);
        gate_kernel<<<dim3((B_ * H_) / (256 * 4), 1, 2), 256>>>(
            b_izr, b_hzr, b_it, b_ht, out, s, phase);
        phase ^= 1;
    }
}